// round 1
// baseline (speedup 1.0000x reference)
#include <cuda_runtime.h>

#define N_NODES_MAX 50000
#define N_EDGES_MAX 800000
#define F 128

// ---------- scratch (device globals; no allocation allowed) ----------
__device__ int   g_deg_out[N_NODES_MAX];
__device__ int   g_deg_in[N_NODES_MAX];
__device__ int   g_counter[N_NODES_MAX];
__device__ int   g_row_ptr[N_NODES_MAX + 1];
__device__ int   g_col_idx[N_EDGES_MAX];
__device__ float g_y[(size_t)N_NODES_MAX * F];

// ---------- 1. zero degree/counter arrays ----------
__global__ void zero_kernel(int n) {
    int i = blockIdx.x * blockDim.x + threadIdx.x;
    if (i < n) {
        g_deg_out[i] = 0;
        g_deg_in[i]  = 0;
        g_counter[i] = 0;
    }
}

// ---------- 2. degree histogram ----------
__global__ void degree_kernel(const int* __restrict__ src,
                              const int* __restrict__ dst, int e) {
    int i = blockIdx.x * blockDim.x + threadIdx.x;
    if (i < e) {
        atomicAdd(&g_deg_out[src[i]], 1);
        atomicAdd(&g_deg_in[dst[i]], 1);
    }
}

// ---------- 3. exclusive scan of deg_in -> row_ptr (single block) ----------
__global__ void scan_kernel(int n) {
    __shared__ int s[1024];
    int tid = threadIdx.x;
    int chunk = (n + 1023) >> 10;
    int start = min(tid * chunk, n);
    int end   = min(start + chunk, n);
    int sum = 0;
    for (int i = start; i < end; i++) sum += g_deg_in[i];
    s[tid] = sum;
    __syncthreads();
    // Hillis-Steele inclusive scan over block sums
    for (int off = 1; off < 1024; off <<= 1) {
        int v = (tid >= off) ? s[tid - off] : 0;
        __syncthreads();
        s[tid] += v;
        __syncthreads();
    }
    int off = (tid == 0) ? 0 : s[tid - 1];
    for (int i = start; i < end; i++) {
        g_row_ptr[i] = off;
        off += g_deg_in[i];
    }
    if (tid == 1023) g_row_ptr[n] = s[1023];
}

// ---------- 4. scatter edges into CSR (sorted by dst) ----------
__global__ void fill_kernel(const int* __restrict__ src,
                            const int* __restrict__ dst, int e) {
    int i = blockIdx.x * blockDim.x + threadIdx.x;
    if (i < e) {
        int d = dst[i];
        int p = atomicAdd(&g_counter[d], 1);
        g_col_idx[g_row_ptr[d] + p] = src[i];
    }
}

// ---------- 5. y = (x * rsqrt(max(deg_out,1))) @ W ----------
// Block tile: 128 rows x 128 cols, 256 threads, 8x8 register tile each.
// K = 128 fits entirely; W tile + A tile live in dynamic smem.
#define BM 128
#define AP 132   // padded A row stride (multiple of 4 for float4 stores)
#define GEMM_SMEM_BYTES ((BM * AP + 128 * 128) * 4)

__global__ void gemm_kernel(const float* __restrict__ x,
                            const float* __restrict__ W, int n) {
    extern __shared__ float smem[];
    float* As = smem;               // [BM][AP]
    float* Bs = smem + BM * AP;     // [128][128]

    int tid  = threadIdx.x;              // 0..255
    int base = blockIdx.x * BM;
    int r0 = tid >> 5;                   // 0..7
    int c0 = (tid & 31) << 2;            // 0..124

#pragma unroll
    for (int p = 0; p < 16; p++) {
        int r = r0 + (p << 3);
        // W load (coalesced, L2-hit for all but first block)
        *(float4*)&Bs[r * 128 + c0] = *(const float4*)&W[r * 128 + c0];
        // A load with left-norm prescale
        int gr = base + r;
        float4 v = make_float4(0.f, 0.f, 0.f, 0.f);
        if (gr < n) {
            v = *(const float4*)&x[(size_t)gr * F + c0];
            float sc = rsqrtf(fmaxf((float)g_deg_out[gr], 1.0f));
            v.x *= sc; v.y *= sc; v.z *= sc; v.w *= sc;
        }
        *(float4*)&As[r * AP + c0] = v;
    }
    __syncthreads();

    int tx = tid & 15;    // output col group
    int ty = tid >> 4;    // output row group
    float acc[8][8];
#pragma unroll
    for (int i = 0; i < 8; i++)
#pragma unroll
        for (int j = 0; j < 8; j++) acc[i][j] = 0.f;

#pragma unroll 8
    for (int k = 0; k < 128; k++) {
        float a[8], b[8];
#pragma unroll
        for (int i = 0; i < 8; i++) a[i] = As[(ty * 8 + i) * AP + k];
        *(float4*)&b[0] = *(float4*)&Bs[k * 128 + tx * 8];
        *(float4*)&b[4] = *(float4*)&Bs[k * 128 + tx * 8 + 4];
#pragma unroll
        for (int i = 0; i < 8; i++)
#pragma unroll
            for (int j = 0; j < 8; j++) acc[i][j] += a[i] * b[j];
    }

#pragma unroll
    for (int i = 0; i < 8; i++) {
        int gr = base + ty * 8 + i;
        if (gr < n) {
            float4 o0 = make_float4(acc[i][0], acc[i][1], acc[i][2], acc[i][3]);
            float4 o1 = make_float4(acc[i][4], acc[i][5], acc[i][6], acc[i][7]);
            *(float4*)&g_y[(size_t)gr * F + tx * 8]     = o0;
            *(float4*)&g_y[(size_t)gr * F + tx * 8 + 4] = o1;
        }
    }
}

// ---------- 6. aggregation + right-norm + bias (one warp per node) ----------
__global__ void agg_kernel(const float* __restrict__ bias,
                           float* __restrict__ out, int n) {
    int node = (blockIdx.x * blockDim.x + threadIdx.x) >> 5;
    int lane = threadIdx.x & 31;
    if (node >= n) return;

    int beg = g_row_ptr[node];
    int end = g_row_ptr[node + 1];

    float4 acc = make_float4(0.f, 0.f, 0.f, 0.f);
    int j = beg;
    // 32-edge chunks: coalesced index load + shfl broadcast
    while (j + 32 <= end) {
        int idx = g_col_idx[j + lane];
#pragma unroll
        for (int i = 0; i < 32; i++) {
            int s = __shfl_sync(0xffffffffu, idx, i);
            float4 v = *(const float4*)(g_y + ((size_t)s << 7) + (lane << 2));
            acc.x += v.x; acc.y += v.y; acc.z += v.z; acc.w += v.w;
        }
        j += 32;
    }
    int rem = end - j;
    if (rem > 0) {
        int idx = (lane < rem) ? g_col_idx[j + lane] : 0;
        for (int i = 0; i < rem; i++) {
            int s = __shfl_sync(0xffffffffu, idx, i);
            float4 v = *(const float4*)(g_y + ((size_t)s << 7) + (lane << 2));
            acc.x += v.x; acc.y += v.y; acc.z += v.z; acc.w += v.w;
        }
    }

    float sc = rsqrtf(fmaxf((float)(end - beg), 1.0f));
    float4 b = ((const float4*)bias)[lane];
    float4 o = make_float4(acc.x * sc + b.x, acc.y * sc + b.y,
                           acc.z * sc + b.z, acc.w * sc + b.w);
    *(float4*)(out + ((size_t)node << 7) + (lane << 2)) = o;
}

// ---------- launch ----------
extern "C" void kernel_launch(void* const* d_in, const int* in_sizes, int n_in,
                              void* d_out, int out_size) {
    const float* x    = (const float*)d_in[0];
    const int*   src  = (const int*)d_in[1];
    const int*   dst  = (const int*)d_in[2];
    const float* W    = (const float*)d_in[3];
    const float* bias = (const float*)d_in[4];
    float* out = (float*)d_out;

    int n = in_sizes[0] / F;
    int e = in_sizes[1];

    cudaFuncSetAttribute(gemm_kernel,
                         cudaFuncAttributeMaxDynamicSharedMemorySize,
                         GEMM_SMEM_BYTES);

    zero_kernel<<<(n + 255) / 256, 256>>>(n);
    degree_kernel<<<(e + 255) / 256, 256>>>(src, dst, e);
    scan_kernel<<<1, 1024>>>(n);
    fill_kernel<<<(e + 255) / 256, 256>>>(src, dst, e);
    gemm_kernel<<<(n + BM - 1) / BM, 256, GEMM_SMEM_BYTES>>>(x, W, n);
    agg_kernel<<<(n * 32 + 255) / 256, 256>>>(bias, out, n);
}